// round 15
// baseline (speedup 1.0000x reference)
#include <cuda_runtime.h>
#include <cstdint>

// ---------------- model constants ----------------
#define BB 16
#define N0 512
#define N1 256
#define N2 128
#define F0c 64
#define F1c 128
#define F2c 256
#define KK 8
#define FC_OUT 512
#define FLATD (N2 * F2c)        // 32768
#define EPSC 1e-9f
#define ZCUT 18.0f

// ---------------- scratch (device globals, no allocs) ----------------
__device__ float g_X0[BB * N0 * (F0c + KK * F0c)];   // [8192, 576]
__device__ float g_H0p[BB * N1 * F1c];
__device__ float g_C1[BB * N1 * 3];
__device__ float g_X1[BB * N1 * (F1c + KK * F1c)];   // [4096, 1152]
__device__ float g_Flat[BB * N2 * F2c];
__device__ float g_part[256][BB * FC_OUT];

// ---------------- helpers ----------------
__device__ __forceinline__ void mma8(float* c,
        uint32_t a0, uint32_t a1, uint32_t a2, uint32_t a3,
        uint32_t b0, uint32_t b1) {
    asm volatile(
        "mma.sync.aligned.m16n8k8.row.col.f32.tf32.tf32.f32 "
        "{%0,%1,%2,%3},{%4,%5,%6,%7},{%8,%9},{%0,%1,%2,%3};"
        : "+f"(c[0]), "+f"(c[1]), "+f"(c[2]), "+f"(c[3])
        : "r"(a0), "r"(a1), "r"(a2), "r"(a3), "r"(b0), "r"(b1));
}
__device__ __forceinline__ uint32_t smem_u32(const void* p) {
    return (uint32_t)__cvta_generic_to_shared(p);
}
__device__ __forceinline__ void cp_async16(uint32_t saddr, const void* gptr) {
    asm volatile("cp.async.ca.shared.global [%0], [%1], 16;"
                 :: "r"(saddr), "l"(gptr));
}
#define CP_COMMIT() asm volatile("cp.async.commit_group;" ::: "memory")
#define CP_WAIT0()  asm volatile("cp.async.wait_group 0;" ::: "memory")

// =================================================================
// Fused message passing, 512 threads (16 warps).
//   msg0: F=64,  TI=64  (512 GEMM rows/block)
//   msg1: F=128, TI=32  (256 GEMM rows/block)
// Per-warp tile WM=64 x WN=32 (TM=4, TN=4, acc=64 regs) for both.
// Builder: warp w owns columns {2w, 2w+1}; iter s -> jj=2w+(s&1),
// i=(s>>1)*32+lane. Single barrier per j-tile; V via cp.async.
// =================================================================
template <int F, int TI>
struct MsgSmem {
    float4 Ci[TI];
    float  Rni[TI];
    float  U[TI][KK];
    float  W[TI][KK];
    float  Umin[TI];
    alignas(16) uint32_t A[2][32][TI * 8 + 8];   // AT: [j][m=i*8+k]
    alignas(16) uint32_t Vt[2][32][F + 8];       // [j][f]
    unsigned short wIdx[16][TI * 2];
    float  wD2[16][TI * 2];
    float  wCs[16][TI * 2];
};

template <int F, int N, int TI>
__global__ __launch_bounds__(512, 1) void msg_kernel(
        const float* __restrict__ V, const float* __restrict__ C,
        const float* __restrict__ gkw, const float* __restrict__ gkb,
        const float* __restrict__ acw, const float* __restrict__ acb,
        float* __restrict__ X) {
    constexpr int TJ = 32, XW = F + KK * F;
    constexpr int MROWS = TI * 8;
    constexpr int WARPS_N = F / 32;          // 2 (F=64) or 4 (F=128)
    constexpr int WARPS_M = 16 / WARPS_N;    // 8 or 4
    constexpr int WM = MROWS / WARPS_M;      // 64
    constexpr int WN = 32;
    constexpr int TM = WM / 16;              // 4
    constexpr int TN = WN / 8;               // 4
    constexpr int VLD = TJ * (F / 4) / 512;  // 1 or 2
    constexpr int T = N / TJ;
    constexpr int NIT = TI / 16;             // 2 (TI=32) or 4 (TI=64)

    extern __shared__ char smem_raw[];
    auto& S = *reinterpret_cast<MsgSmem<F, TI>*>(smem_raw);

    const int b = blockIdx.y;
    const int i0 = blockIdx.x * TI;
    const int tid = threadIdx.x;
    const int wid = tid >> 5, lane = tid & 31;
    const int g = lane >> 2, cc = lane & 3;
    const int warp_m = wid / WARPS_N, warp_n = wid % WARPS_N;

    // ---- setup ----
    if (tid < TI) {
        int i = i0 + tid;
        float x = C[((size_t)b * N + i) * 3 + 0];
        float y = C[((size_t)b * N + i) * 3 + 1];
        float z = C[((size_t)b * N + i) * 3 + 2];
        float l2 = x * x + y * y + z * z;
        S.Ci[tid] = make_float4(x, y, z, l2);
        S.Rni[tid] = rsqrtf(l2 + EPSC);
    }
    if (TI == 32) {   // 512 threads = 2 gates x 32 rows x 8 k
        int gate = tid >> 8;
        int r = (tid >> 3) & 31;
        int k = tid & 7;
        const float* wgt = gate ? acw : gkw;
        float s = gate ? acb[k] : gkb[k];
        const float* vrow = V + ((size_t)b * N + i0 + r) * F;
#pragma unroll 8
        for (int f = 0; f < F; ++f) s += vrow[f] * wgt[f * KK + k];
        if (gate) {
            S.W[r][k] = 1.f / (1.f + __expf(-s));
        } else {
            float u = fmaxf(s, 0.f) + log1pf(__expf(-fabsf(s)));
            S.U[r][k] = u;
            float um = u;
            um = fminf(um, __shfl_xor_sync(0xffffffffu, um, 1));
            um = fminf(um, __shfl_xor_sync(0xffffffffu, um, 2));
            um = fminf(um, __shfl_xor_sync(0xffffffffu, um, 4));
            if (k == 0) S.Umin[r] = um;
        }
    } else {          // TI=64: 512 threads = 64 rows x 8 k, both gates
        int r = tid >> 3;
        int k = tid & 7;
        float su = gkb[k], sw = acb[k];
        const float* vrow = V + ((size_t)b * N + i0 + r) * F;
#pragma unroll 8
        for (int f = 0; f < F; ++f) {
            float vv = vrow[f];
            su += vv * gkw[f * KK + k];
            sw += vv * acw[f * KK + k];
        }
        S.W[r][k] = 1.f / (1.f + __expf(-sw));
        float u = fmaxf(su, 0.f) + log1pf(__expf(-fabsf(su)));
        S.U[r][k] = u;
        float um = u;
        um = fminf(um, __shfl_xor_sync(0xffffffffu, um, 1));
        um = fminf(um, __shfl_xor_sync(0xffffffffu, um, 2));
        um = fminf(um, __shfl_xor_sync(0xffffffffu, um, 4));
        if (k == 0) S.Umin[r] = um;
    }
    // copy V rows into first F cols of X
    for (int t = tid; t < TI * (F / 4); t += 512) {
        int i = t / (F / 4), fq = t % (F / 4);
        float4 vv = reinterpret_cast<const float4*>(V + ((size_t)b * N + i0 + i) * F)[fq];
        reinterpret_cast<float4*>(X + ((size_t)b * N + i0 + i) * XW)[fq] = vv;
    }
    __syncthreads();   // gates/Ci visible

    auto issueV = [&](int buf, int j0) {
#pragma unroll
        for (int s = 0; s < VLD; ++s) {
            int idx = tid + s * 512;
            int j = idx / (F / 4), fq = idx % (F / 4);
            cp_async16(smem_u32(&S.Vt[buf][j][fq * 4]),
                       V + ((size_t)b * N + j0 + j) * F + fq * 4);
        }
        CP_COMMIT();
    };

    // builder: warp w owns cols {2w, 2w+1}; iter s -> jj=2w+(s&1), i=(s>>1)*32+lane
    auto build = [&](int buf, const float* cxa, const float* cya, const float* cza) {
        int wcnt = 0;
#pragma unroll
        for (int s = 0; s < NIT; ++s) {
            int i = (s >> 1) * 32 + lane;
            int jj = wid * 2 + (s & 1);
            float cx = cxa[s], cy = cya[s], cz = cza[s];
            float l2 = cx * cx + cy * cy + cz * cz;
            float4 ci = S.Ci[i];
            float dot = ci.x * cx + ci.y * cy + ci.z * cz;
            float d2 = fabsf(ci.w + l2 - 2.f * dot) + EPSC;
            bool near = (d2 * S.Umin[i] <= ZCUT);
            if (!near) {
                uint4 z = make_uint4(0u, 0u, 0u, 0u);
                *reinterpret_cast<uint4*>(&S.A[buf][jj][i * 8 + 0]) = z;
                *reinterpret_cast<uint4*>(&S.A[buf][jj][i * 8 + 4]) = z;
            }
            unsigned mask = __ballot_sync(0xffffffffu, near);
            if (near) {
                int slot = wcnt + __popc(mask & ((1u << lane) - 1u));
                S.wIdx[wid][slot] = (unsigned short)((i << 5) | jj);
                S.wD2[wid][slot] = d2;
                S.wCs[wid][slot] = dot * S.Rni[i] * rsqrtf(l2 + EPSC);
            }
            wcnt += __popc(mask);
        }
        __syncwarp();
        const int work = wcnt * 2;
        for (int t = lane; t < work; t += 32) {
            int e = t >> 1, h = t & 1;
            int p = S.wIdx[wid][e];
            int i = p >> 5, jj = p & 31;
            float d2 = S.wD2[wid][e], cs = S.wCs[wid][e];
            float4 uu = *reinterpret_cast<const float4*>(&S.U[i][h * 4]);
            float4 ww = *reinterpret_cast<const float4*>(&S.W[i][h * 4]);
            uint4 o;
            { float z = d2 * uu.x; float ex = (z > ZCUT) ? 0.f : __expf(-z);
              o.x = __float_as_uint(ex * (ww.x * cs + 1.f - ww.x)); }
            { float z = d2 * uu.y; float ex = (z > ZCUT) ? 0.f : __expf(-z);
              o.y = __float_as_uint(ex * (ww.y * cs + 1.f - ww.y)); }
            { float z = d2 * uu.z; float ex = (z > ZCUT) ? 0.f : __expf(-z);
              o.z = __float_as_uint(ex * (ww.z * cs + 1.f - ww.z)); }
            { float z = d2 * uu.w; float ex = (z > ZCUT) ? 0.f : __expf(-z);
              o.w = __float_as_uint(ex * (ww.w * cs + 1.f - ww.w)); }
            *reinterpret_cast<uint4*>(&S.A[buf][jj][i * 8 + h * 4]) = o;
        }
    };

    {
        issueV(0, 0);
        float cxa[NIT], cya[NIT], cza[NIT];
#pragma unroll
        for (int s = 0; s < NIT; ++s) {
            int jj = wid * 2 + (s & 1);
            const float* cp = C + ((size_t)b * N + jj) * 3;
            cxa[s] = cp[0]; cya[s] = cp[1]; cza[s] = cp[2];
        }
        build(0, cxa, cya, cza);
        CP_WAIT0();
    }
    __syncthreads();

    float acc[TM][TN][4];
#pragma unroll
    for (int tm = 0; tm < TM; ++tm)
#pragma unroll
        for (int tn = 0; tn < TN; ++tn)
#pragma unroll
            for (int q = 0; q < 4; ++q) acc[tm][tn][q] = 0.f;

    for (int t = 0; t < T; ++t) {
        const int cur = t & 1, nxt = cur ^ 1;
        const bool more = (t + 1 < T);
        float cxa[NIT], cya[NIT], cza[NIT];
        if (more) {
            int j0n = (t + 1) * TJ;
            issueV(nxt, j0n);
#pragma unroll
            for (int s = 0; s < NIT; ++s) {
                int jj = wid * 2 + (s & 1);
                const float* cp = C + ((size_t)b * N + j0n + jj) * 3;
                cxa[s] = cp[0]; cya[s] = cp[1]; cza[s] = cp[2];
            }
        }
#pragma unroll
        for (int ks = 0; ks < 4; ++ks) {
            uint32_t af[TM][4];
#pragma unroll
            for (int tm = 0; tm < TM; ++tm) {
                int r = warp_m * WM + tm * 16;
                af[tm][0] = S.A[cur][ks * 8 + cc][r + g];
                af[tm][1] = S.A[cur][ks * 8 + cc][r + g + 8];
                af[tm][2] = S.A[cur][ks * 8 + cc + 4][r + g];
                af[tm][3] = S.A[cur][ks * 8 + cc + 4][r + g + 8];
            }
#pragma unroll
            for (int tn = 0; tn < TN; ++tn) {
                int nb = warp_n * WN + tn * 8;
                uint32_t b0 = S.Vt[cur][ks * 8 + cc][nb + g];
                uint32_t b1 = S.Vt[cur][ks * 8 + cc + 4][nb + g];
#pragma unroll
                for (int tm = 0; tm < TM; ++tm)
                    mma8(acc[tm][tn], af[tm][0], af[tm][1], af[tm][2], af[tm][3], b0, b1);
            }
        }
        if (more) {
            build(nxt, cxa, cya, cza);
            CP_WAIT0();
        }
        __syncthreads();
    }

    // write M section of X: GEMM row m = i*8+k
#pragma unroll
    for (int tm = 0; tm < TM; ++tm) {
#pragma unroll
        for (int half = 0; half < 2; ++half) {
            int m = warp_m * WM + tm * 16 + g + half * 8;
            int i = m >> 3, k = m & 7;
            float* xr = X + ((size_t)b * N + i0 + i) * XW + F + k * F + warp_n * WN;
#pragma unroll
            for (int tn = 0; tn < TN; ++tn) {
                float2 o;
                o.x = acc[tm][tn][half * 2 + 0];
                o.y = acc[tm][tn][half * 2 + 1];
                *reinterpret_cast<float2*>(xr + tn * 8 + 2 * cc) = o;
            }
        }
    }
}

// =================================================================
// tf32 GEMM + tanh + BN + fused 2:1 row pooling (R11, frozen)
// =================================================================
struct GemmSmem {
    alignas(16) uint32_t As[2][128][36];
    alignas(16) uint32_t Bs[2][32][72];
};

template <int NIN>
__global__ __launch_bounds__(256) void gemm_pool(
        const float* __restrict__ A, const float* __restrict__ Wt,
        const float* __restrict__ bias, const float* __restrict__ bng,
        const float* __restrict__ bnb, float* __restrict__ Out,
        int Kd, int Nc) {
    constexpr int BM = 128, BN = 64, BK = 32;
    constexpr int TM = 2, TN = 4;
    extern __shared__ char smem_raw[];
    auto& S = *reinterpret_cast<GemmSmem*>(smem_raw);
    const int bm = blockIdx.y * BM, bn = blockIdx.x * BN;
    const int tid = threadIdx.x, wid = tid >> 5, lane = tid & 31;
    const int g = lane >> 2, cc = lane & 3;
    const int warp_m = wid >> 1, warp_n = wid & 1;

    float acc[TM][TN][4];
#pragma unroll
    for (int tm = 0; tm < TM; ++tm)
#pragma unroll
        for (int tn = 0; tn < TN; ++tn)
#pragma unroll
            for (int q = 0; q < 4; ++q) acc[tm][tn][q] = 0.f;

    const int nk = Kd / BK;

    auto issueTile = [&](int buf, int k0) {
#pragma unroll
        for (int s = 0; s < 4; ++s) {
            int idx = tid + s * 256, r = idx >> 3, cq = idx & 7;
            cp_async16(smem_u32(&S.As[buf][r][cq * 4]),
                       A + (size_t)(bm + r) * Kd + k0 + cq * 4);
        }
#pragma unroll
        for (int s = 0; s < 2; ++s) {
            int idx = tid + s * 256, kr = idx >> 4, cq = idx & 15;
            cp_async16(smem_u32(&S.Bs[buf][kr][cq * 4]),
                       Wt + (size_t)(k0 + kr) * Nc + bn + cq * 4);
        }
        CP_COMMIT();
    };

    issueTile(0, 0);
    CP_WAIT0();
    __syncthreads();

    for (int kt = 0; kt < nk; ++kt) {
        const int cur = kt & 1, nxt = cur ^ 1;
        const bool more = (kt + 1 < nk);
        if (more) issueTile(nxt, (kt + 1) * BK);
#pragma unroll
        for (int ks = 0; ks < 4; ++ks) {
            uint32_t af[TM][4];
#pragma unroll
            for (int tm = 0; tm < TM; ++tm) {
                int r = warp_m * 32 + tm * 16;
                af[tm][0] = S.As[cur][r + g][ks * 8 + cc];
                af[tm][1] = S.As[cur][r + g + 8][ks * 8 + cc];
                af[tm][2] = S.As[cur][r + g][ks * 8 + cc + 4];
                af[tm][3] = S.As[cur][r + g + 8][ks * 8 + cc + 4];
            }
#pragma unroll
            for (int tn = 0; tn < TN; ++tn) {
                int nb = warp_n * 32 + tn * 8;
                uint32_t b0 = S.Bs[cur][ks * 8 + cc][nb + g];
                uint32_t b1 = S.Bs[cur][ks * 8 + cc + 4][nb + g];
#pragma unroll
                for (int tm = 0; tm < TM; ++tm)
                    mma8(acc[tm][tn], af[tm][0], af[tm][1], af[tm][2], af[tm][3], b0, b1);
            }
        }
        if (more) CP_WAIT0();
        __syncthreads();
    }

    const bool wr = ((g & 1) == 0);
#pragma unroll
    for (int tm = 0; tm < TM; ++tm) {
#pragma unroll
        for (int half = 0; half < 2; ++half) {
            int r = bm + warp_m * 32 + tm * 16 + g + half * 8;
#pragma unroll
            for (int tn = 0; tn < TN; ++tn) {
                int col = bn + warp_n * 32 + tn * 8 + 2 * cc;
                float h0 = bng[col] * tanhf(acc[tm][tn][half * 2 + 0] + bias[col]) + bnb[col];
                float h1 = bng[col + 1] * tanhf(acc[tm][tn][half * 2 + 1] + bias[col + 1]) + bnb[col + 1];
                float p0 = 0.5f * (h0 + __shfl_down_sync(0xffffffffu, h0, 4));
                float p1 = 0.5f * (h1 + __shfl_down_sync(0xffffffffu, h1, 4));
                if (wr) {
                    int pr = (r / NIN) * (NIN / 2) + (r % NIN) / 2;
                    *reinterpret_cast<float2*>(Out + (size_t)pr * Nc + col) =
                        make_float2(p0, p1);
                }
            }
        }
    }
}

// ---------------- coord pooling (tiny) ----------------
__global__ void poolC_kernel(const float* __restrict__ C, float* __restrict__ C1) {
    int idx = blockIdx.x * blockDim.x + threadIdx.x;
    if (idx >= BB * N1 * 3) return;
    int c = idx % 3;
    int i = (idx / 3) % N1;
    int b = idx / (3 * N1);
    size_t base = ((size_t)b * N0 + 2 * i) * 3 + c;
    C1[idx] = 0.5f * (C[base] + C[base + 3]);
}

// ---------------- FC: split-K partials (fp32, deterministic) ----------------
__global__ __launch_bounds__(128) void fc_partial(const float* __restrict__ Flat,
                                                  const float* __restrict__ W) {
    constexpr int KCH = FLATD / 256;   // 128
    const int kb = blockIdx.x * KCH;
    const int tid = threadIdx.x;
    __shared__ float sF[BB][KCH];
    for (int t = tid; t < BB * KCH / 4; t += 128) {
        int b = t / (KCH / 4), kq = t % (KCH / 4);
        *reinterpret_cast<float4*>(&sF[b][kq * 4]) =
            *reinterpret_cast<const float4*>(Flat + (size_t)b * FLATD + kb + kq * 4);
    }
    __syncthreads();

    float4 acc[BB];
#pragma unroll
    for (int b = 0; b < BB; ++b) acc[b] = make_float4(0.f, 0.f, 0.f, 0.f);

    const float* wp = W + (size_t)kb * FC_OUT + tid * 4;
    for (int k = 0; k < KCH; k += 4) {
        float4 w0 = *reinterpret_cast<const float4*>(wp + (size_t)(k + 0) * FC_OUT);
        float4 w1 = *reinterpret_cast<const float4*>(wp + (size_t)(k + 1) * FC_OUT);
        float4 w2 = *reinterpret_cast<const float4*>(wp + (size_t)(k + 2) * FC_OUT);
        float4 w3 = *reinterpret_cast<const float4*>(wp + (size_t)(k + 3) * FC_OUT);
#pragma unroll
        for (int b = 0; b < BB; ++b) {
            float4 f = *reinterpret_cast<float4*>(&sF[b][k]);
            acc[b].x += f.x * w0.x + f.y * w1.x + f.z * w2.x + f.w * w3.x;
            acc[b].y += f.x * w0.y + f.y * w1.y + f.z * w2.y + f.w * w3.y;
            acc[b].z += f.x * w0.z + f.y * w1.z + f.z * w2.z + f.w * w3.z;
            acc[b].w += f.x * w0.w + f.y * w1.w + f.z * w2.w + f.w * w3.w;
        }
    }
#pragma unroll
    for (int b = 0; b < BB; ++b)
        *reinterpret_cast<float4*>(&g_part[blockIdx.x][b * FC_OUT + tid * 4]) = acc[b];
}

__global__ void fc_finalize(const float* __restrict__ fcb, float* __restrict__ out) {
    int idx = blockIdx.x * blockDim.x + threadIdx.x;
    if (idx >= BB * FC_OUT) return;
    int col = idx & (FC_OUT - 1);
    float s = fcb[col];
#pragma unroll 8
    for (int t = 0; t < 256; ++t) s += g_part[t][idx];
    out[idx] = 1.f / (1.f + __expf(-s));
}

// ---------------- launch ----------------
extern "C" void kernel_launch(void* const* d_in, const int* in_sizes, int n_in,
                              void* d_out, int out_size) {
    const float* V    = (const float*)d_in[0];
    const float* C    = (const float*)d_in[1];
    const float* gkw0 = (const float*)d_in[2];
    const float* gkb0 = (const float*)d_in[3];
    const float* acw0 = (const float*)d_in[4];
    const float* acb0 = (const float*)d_in[5];
    const float* gcw0 = (const float*)d_in[6];
    const float* gcb0 = (const float*)d_in[7];
    const float* bng0 = (const float*)d_in[8];
    const float* bnb0 = (const float*)d_in[9];
    const float* gkw1 = (const float*)d_in[10];
    const float* gkb1 = (const float*)d_in[11];
    const float* acw1 = (const float*)d_in[12];
    const float* acb1 = (const float*)d_in[13];
    const float* gcw1 = (const float*)d_in[14];
    const float* gcb1 = (const float*)d_in[15];
    const float* bng1 = (const float*)d_in[16];
    const float* bnb1 = (const float*)d_in[17];
    const float* fcw  = (const float*)d_in[18];
    const float* fcb  = (const float*)d_in[19];
    float* out = (float*)d_out;

    float *X0, *H0p, *C1, *X1, *Flat;
    cudaGetSymbolAddress((void**)&X0, g_X0);
    cudaGetSymbolAddress((void**)&H0p, g_H0p);
    cudaGetSymbolAddress((void**)&C1, g_C1);
    cudaGetSymbolAddress((void**)&X1, g_X1);
    cudaGetSymbolAddress((void**)&Flat, g_Flat);

    const int smsg0 = (int)sizeof(MsgSmem<F0c, 64>);
    const int smsg1 = (int)sizeof(MsgSmem<F1c, 32>);
    const int sgemm = (int)sizeof(GemmSmem);
    cudaFuncSetAttribute(msg_kernel<F0c, N0, 64>,
                         cudaFuncAttributeMaxDynamicSharedMemorySize, smsg0);
    cudaFuncSetAttribute(msg_kernel<F1c, N1, 32>,
                         cudaFuncAttributeMaxDynamicSharedMemorySize, smsg1);
    cudaFuncSetAttribute(gemm_pool<N0>,
                         cudaFuncAttributeMaxDynamicSharedMemorySize, sgemm);
    cudaFuncSetAttribute(gemm_pool<N1>,
                         cudaFuncAttributeMaxDynamicSharedMemorySize, sgemm);

    // layer 0 (msg0: TI=64, 512 threads, 128 blocks)
    msg_kernel<F0c, N0, 64><<<dim3(N0 / 64, BB), 512, smsg0>>>(
        V, C, gkw0, gkb0, acw0, acb0, X0);
    gemm_pool<N0><<<dim3(F1c / 64, BB * N0 / 128), 256, sgemm>>>(
        X0, gcw0, gcb0, bng0, bnb0, H0p, (KK + 1) * F0c, F1c);
    poolC_kernel<<<(BB * N1 * 3 + 255) / 256, 256>>>(C, C1);

    // layer 1 (msg1: TI=32, 512 threads, 128 blocks)
    msg_kernel<F1c, N1, 32><<<dim3(N1 / 32, BB), 512, smsg1>>>(
        H0p, C1, gkw1, gkb1, acw1, acb1, X1);
    gemm_pool<N1><<<dim3(F2c / 64, BB * N1 / 128), 256, sgemm>>>(
        X1, gcw1, gcb1, bng1, bnb1, Flat, (KK + 1) * F1c, F2c);

    // FC head (fp32)
    fc_partial<<<256, 128>>>(Flat, fcw);
    fc_finalize<<<(BB * FC_OUT + 255) / 256, 256>>>(fcb, out);
}

// round 16
// speedup vs baseline: 1.0250x; 1.0250x over previous
#include <cuda_runtime.h>
#include <cstdint>

// ---------------- model constants ----------------
#define BB 16
#define N0 512
#define N1 256
#define N2 128
#define F0c 64
#define F1c 128
#define F2c 256
#define KK 8
#define FC_OUT 512
#define FLATD (N2 * F2c)        // 32768
#define EPSC 1e-9f
#define ZCUT 18.0f

// ---------------- scratch (device globals, no allocs) ----------------
__device__ float g_X0[BB * N0 * (F0c + KK * F0c)];   // [8192, 576]
__device__ float g_H0p[BB * N1 * F1c];
__device__ float g_C1[BB * N1 * 3];
__device__ float g_X1[BB * N1 * (F1c + KK * F1c)];   // [4096, 1152]
__device__ float g_Flat[BB * N2 * F2c];
__device__ float g_part[256][BB * FC_OUT];

// ---------------- helpers ----------------
__device__ __forceinline__ void mma8(float* c,
        uint32_t a0, uint32_t a1, uint32_t a2, uint32_t a3,
        uint32_t b0, uint32_t b1) {
    asm volatile(
        "mma.sync.aligned.m16n8k8.row.col.f32.tf32.tf32.f32 "
        "{%0,%1,%2,%3},{%4,%5,%6,%7},{%8,%9},{%0,%1,%2,%3};"
        : "+f"(c[0]), "+f"(c[1]), "+f"(c[2]), "+f"(c[3])
        : "r"(a0), "r"(a1), "r"(a2), "r"(a3), "r"(b0), "r"(b1));
}
__device__ __forceinline__ uint32_t smem_u32(const void* p) {
    return (uint32_t)__cvta_generic_to_shared(p);
}
__device__ __forceinline__ void cp_async16(uint32_t saddr, const void* gptr) {
    asm volatile("cp.async.ca.shared.global [%0], [%1], 16;"
                 :: "r"(saddr), "l"(gptr));
}
#define CP_COMMIT() asm volatile("cp.async.commit_group;" ::: "memory")
#define CP_WAIT0()  asm volatile("cp.async.wait_group 0;" ::: "memory")

// =================================================================
// Fused message passing (R14 config):
//   msg0: F=64,  TI=32, 256 thr  (+ fused coord pooling C->C1)
//   msg1: F=128, TI=16, 256 thr
// =================================================================
template <int F, int TI>
struct MsgSmem {
    float4 Ci[TI];
    float  Rni[TI];
    float  U[TI][KK];
    float  W[TI][KK];
    float  Umin[TI];
    alignas(16) uint32_t A[2][32][TI * 8 + 8];   // AT: [j][m=i*8+k]
    alignas(16) uint32_t Vt[2][32][F + 8];       // [j][f]
    unsigned short wIdx[8][TI * 4];
    float  wD2[8][TI * 4];
    float  wCs[8][TI * 4];
};

template <int F, int N, int TI>
__global__ __launch_bounds__(256, 2) void msg_kernel(
        const float* __restrict__ V, const float* __restrict__ C,
        const float* __restrict__ gkw, const float* __restrict__ gkb,
        const float* __restrict__ acw, const float* __restrict__ acb,
        float* __restrict__ X, float* __restrict__ C1out) {
    constexpr int TJ = 32, XW = F + KK * F;
    constexpr int MROWS = TI * 8;
    constexpr int WARPS_N = F / 32;         // 2 (F=64) or 4 (F=128)
    constexpr int WARPS_M = 8 / WARPS_N;    // 4 or 2
    constexpr int WM = MROWS / WARPS_M;     // 64
    constexpr int WN = 32;
    constexpr int TM = WM / 16;             // 4
    constexpr int TN = WN / 8;              // 4
    constexpr int VLD = TJ * (F / 4) / 256;
    constexpr int T = N / TJ;
    constexpr int NIT = TI / 8;             // 2 or 4

    extern __shared__ char smem_raw[];
    auto& S = *reinterpret_cast<MsgSmem<F, TI>*>(smem_raw);

    const int b = blockIdx.y;
    const int i0 = blockIdx.x * TI;
    const int tid = threadIdx.x;
    const int wid = tid >> 5, lane = tid & 31;
    const int g = lane >> 2, cc = lane & 3;
    const int warp_m = wid / WARPS_N, warp_n = wid % WARPS_N;

    auto bld_i = [&](int s) {
        return (TI == 16) ? (lane & 15) : lane;
    };
    auto bld_jj = [&](int s) {
        int c = (TI == 16) ? (s * 2 + (lane >> 4)) : s;
        return ((c >> 1) << 4) + wid * 2 + (c & 1);
    };

    // ---- fused coord pooling (layer 0 only; C1 consumed 2 launches later) ----
    if (C1out != nullptr && blockIdx.x == 0) {
        for (int t = tid; t < N1 * 3; t += 256) {
            int c = t % 3, i = t / 3;
            size_t base = ((size_t)b * N0 + 2 * i) * 3 + c;
            C1out[(size_t)b * N1 * 3 + t] = 0.5f * (C[base] + C[base + 3]);
        }
    }

    // ---- setup ----
    if (tid < TI) {
        int i = i0 + tid;
        float x = C[((size_t)b * N + i) * 3 + 0];
        float y = C[((size_t)b * N + i) * 3 + 1];
        float z = C[((size_t)b * N + i) * 3 + 2];
        float l2 = x * x + y * y + z * z;
        S.Ci[tid] = make_float4(x, y, z, l2);
        S.Rni[tid] = rsqrtf(l2 + EPSC);
    }
    if (TI == 16) {   // 256 threads = 2 gates x 16 rows x 8 k
        int gate = tid >> 7;
        int r = (tid >> 3) & 15;
        int k = tid & 7;
        const float* wgt = gate ? acw : gkw;
        float s = gate ? acb[k] : gkb[k];
        const float* vrow = V + ((size_t)b * N + i0 + r) * F;
#pragma unroll 8
        for (int f = 0; f < F; ++f) s += vrow[f] * wgt[f * KK + k];
        if (gate) {
            S.W[r][k] = 1.f / (1.f + __expf(-s));
        } else {
            float u = fmaxf(s, 0.f) + log1pf(__expf(-fabsf(s)));
            S.U[r][k] = u;
            float um = u;
            um = fminf(um, __shfl_xor_sync(0xffffffffu, um, 1));
            um = fminf(um, __shfl_xor_sync(0xffffffffu, um, 2));
            um = fminf(um, __shfl_xor_sync(0xffffffffu, um, 4));
            if (k == 0) S.Umin[r] = um;
        }
    } else {          // TI=32: each thread does both gates for (r,k)
        int r = tid >> 3;
        int k = tid & 7;
        float su = gkb[k], sw = acb[k];
        const float* vrow = V + ((size_t)b * N + i0 + r) * F;
#pragma unroll 8
        for (int f = 0; f < F; ++f) {
            float vv = vrow[f];
            su += vv * gkw[f * KK + k];
            sw += vv * acw[f * KK + k];
        }
        S.W[r][k] = 1.f / (1.f + __expf(-sw));
        float u = fmaxf(su, 0.f) + log1pf(__expf(-fabsf(su)));
        S.U[r][k] = u;
        float um = u;
        um = fminf(um, __shfl_xor_sync(0xffffffffu, um, 1));
        um = fminf(um, __shfl_xor_sync(0xffffffffu, um, 2));
        um = fminf(um, __shfl_xor_sync(0xffffffffu, um, 4));
        if (k == 0) S.Umin[r] = um;
    }
    // copy V rows into first F cols of X
    for (int t = tid; t < TI * (F / 4); t += 256) {
        int i = t / (F / 4), fq = t % (F / 4);
        float4 vv = reinterpret_cast<const float4*>(V + ((size_t)b * N + i0 + i) * F)[fq];
        reinterpret_cast<float4*>(X + ((size_t)b * N + i0 + i) * XW)[fq] = vv;
    }
    __syncthreads();

    auto issueV = [&](int buf, int j0) {
#pragma unroll
        for (int s = 0; s < VLD; ++s) {
            int idx = tid + s * 256;
            int j = idx / (F / 4), fq = idx % (F / 4);
            cp_async16(smem_u32(&S.Vt[buf][j][fq * 4]),
                       V + ((size_t)b * N + j0 + j) * F + fq * 4);
        }
        CP_COMMIT();
    };

    auto build = [&](int buf, const float* cxa, const float* cya, const float* cza) {
        int wcnt = 0;
#pragma unroll
        for (int s = 0; s < NIT; ++s) {
            int i = bld_i(s);
            int jj = bld_jj(s);
            float cx = cxa[s], cy = cya[s], cz = cza[s];
            float l2 = cx * cx + cy * cy + cz * cz;
            float4 ci = S.Ci[i];
            float dot = ci.x * cx + ci.y * cy + ci.z * cz;
            float d2 = fabsf(ci.w + l2 - 2.f * dot) + EPSC;
            bool near = (d2 * S.Umin[i] <= ZCUT);
            if (!near) {
                uint4 z = make_uint4(0u, 0u, 0u, 0u);
                *reinterpret_cast<uint4*>(&S.A[buf][jj][i * 8 + 0]) = z;
                *reinterpret_cast<uint4*>(&S.A[buf][jj][i * 8 + 4]) = z;
            }
            unsigned mask = __ballot_sync(0xffffffffu, near);
            if (near) {
                int slot = wcnt + __popc(mask & ((1u << lane) - 1u));
                S.wIdx[wid][slot] = (unsigned short)((i << 5) | jj);
                S.wD2[wid][slot] = d2;
                S.wCs[wid][slot] = dot * S.Rni[i] * rsqrtf(l2 + EPSC);
            }
            wcnt += __popc(mask);
        }
        __syncwarp();
        const int work = wcnt * 2;
        for (int t = lane; t < work; t += 32) {
            int e = t >> 1, h = t & 1;
            int p = S.wIdx[wid][e];
            int i = p >> 5, jj = p & 31;
            float d2 = S.wD2[wid][e], cs = S.wCs[wid][e];
            float4 uu = *reinterpret_cast<const float4*>(&S.U[i][h * 4]);
            float4 ww = *reinterpret_cast<const float4*>(&S.W[i][h * 4]);
            uint4 o;
            { float z = d2 * uu.x; float ex = (z > ZCUT) ? 0.f : __expf(-z);
              o.x = __float_as_uint(ex * (ww.x * cs + 1.f - ww.x)); }
            { float z = d2 * uu.y; float ex = (z > ZCUT) ? 0.f : __expf(-z);
              o.y = __float_as_uint(ex * (ww.y * cs + 1.f - ww.y)); }
            { float z = d2 * uu.z; float ex = (z > ZCUT) ? 0.f : __expf(-z);
              o.z = __float_as_uint(ex * (ww.z * cs + 1.f - ww.z)); }
            { float z = d2 * uu.w; float ex = (z > ZCUT) ? 0.f : __expf(-z);
              o.w = __float_as_uint(ex * (ww.w * cs + 1.f - ww.w)); }
            *reinterpret_cast<uint4*>(&S.A[buf][jj][i * 8 + h * 4]) = o;
        }
    };

    {
        issueV(0, 0);
        float cxa[NIT], cya[NIT], cza[NIT];
#pragma unroll
        for (int s = 0; s < NIT; ++s) {
            int jj = bld_jj(s);
            const float* cp = C + ((size_t)b * N + jj) * 3;
            cxa[s] = cp[0]; cya[s] = cp[1]; cza[s] = cp[2];
        }
        build(0, cxa, cya, cza);
        CP_WAIT0();
    }
    __syncthreads();

    float acc[TM][TN][4];
#pragma unroll
    for (int tm = 0; tm < TM; ++tm)
#pragma unroll
        for (int tn = 0; tn < TN; ++tn)
#pragma unroll
            for (int q = 0; q < 4; ++q) acc[tm][tn][q] = 0.f;

    for (int t = 0; t < T; ++t) {
        const int cur = t & 1, nxt = cur ^ 1;
        const bool more = (t + 1 < T);
        float cxa[NIT], cya[NIT], cza[NIT];
        if (more) {
            int j0n = (t + 1) * TJ;
            issueV(nxt, j0n);
#pragma unroll
            for (int s = 0; s < NIT; ++s) {
                int jj = bld_jj(s);
                const float* cp = C + ((size_t)b * N + j0n + jj) * 3;
                cxa[s] = cp[0]; cya[s] = cp[1]; cza[s] = cp[2];
            }
        }
#pragma unroll
        for (int ks = 0; ks < 4; ++ks) {
            uint32_t af[TM][4];
#pragma unroll
            for (int tm = 0; tm < TM; ++tm) {
                int r = warp_m * WM + tm * 16;
                af[tm][0] = S.A[cur][ks * 8 + cc][r + g];
                af[tm][1] = S.A[cur][ks * 8 + cc][r + g + 8];
                af[tm][2] = S.A[cur][ks * 8 + cc + 4][r + g];
                af[tm][3] = S.A[cur][ks * 8 + cc + 4][r + g + 8];
            }
#pragma unroll
            for (int tn = 0; tn < TN; ++tn) {
                int nb = warp_n * WN + tn * 8;
                uint32_t b0 = S.Vt[cur][ks * 8 + cc][nb + g];
                uint32_t b1 = S.Vt[cur][ks * 8 + cc + 4][nb + g];
#pragma unroll
                for (int tm = 0; tm < TM; ++tm)
                    mma8(acc[tm][tn], af[tm][0], af[tm][1], af[tm][2], af[tm][3], b0, b1);
            }
        }
        if (more) {
            build(nxt, cxa, cya, cza);
            CP_WAIT0();
        }
        __syncthreads();
    }

    // write M section of X: GEMM row m = i*8+k
#pragma unroll
    for (int tm = 0; tm < TM; ++tm) {
#pragma unroll
        for (int half = 0; half < 2; ++half) {
            int m = warp_m * WM + tm * 16 + g + half * 8;
            int i = m >> 3, k = m & 7;
            float* xr = X + ((size_t)b * N + i0 + i) * XW + F + k * F + warp_n * WN;
#pragma unroll
            for (int tn = 0; tn < TN; ++tn) {
                float2 o;
                o.x = acc[tm][tn][half * 2 + 0];
                o.y = acc[tm][tn][half * 2 + 1];
                *reinterpret_cast<float2*>(xr + tn * 8 + 2 * cc) = o;
            }
        }
    }
}

// =================================================================
// tf32 GEMM + tanh + BN + fused 2:1 row pooling (R11, frozen)
// =================================================================
struct GemmSmem {
    alignas(16) uint32_t As[2][128][36];
    alignas(16) uint32_t Bs[2][32][72];
};

template <int NIN>
__global__ __launch_bounds__(256) void gemm_pool(
        const float* __restrict__ A, const float* __restrict__ Wt,
        const float* __restrict__ bias, const float* __restrict__ bng,
        const float* __restrict__ bnb, float* __restrict__ Out,
        int Kd, int Nc) {
    constexpr int BM = 128, BN = 64, BK = 32;
    constexpr int TM = 2, TN = 4;
    extern __shared__ char smem_raw[];
    auto& S = *reinterpret_cast<GemmSmem*>(smem_raw);
    const int bm = blockIdx.y * BM, bn = blockIdx.x * BN;
    const int tid = threadIdx.x, wid = tid >> 5, lane = tid & 31;
    const int g = lane >> 2, cc = lane & 3;
    const int warp_m = wid >> 1, warp_n = wid & 1;

    float acc[TM][TN][4];
#pragma unroll
    for (int tm = 0; tm < TM; ++tm)
#pragma unroll
        for (int tn = 0; tn < TN; ++tn)
#pragma unroll
            for (int q = 0; q < 4; ++q) acc[tm][tn][q] = 0.f;

    const int nk = Kd / BK;

    auto issueTile = [&](int buf, int k0) {
#pragma unroll
        for (int s = 0; s < 4; ++s) {
            int idx = tid + s * 256, r = idx >> 3, cq = idx & 7;
            cp_async16(smem_u32(&S.As[buf][r][cq * 4]),
                       A + (size_t)(bm + r) * Kd + k0 + cq * 4);
        }
#pragma unroll
        for (int s = 0; s < 2; ++s) {
            int idx = tid + s * 256, kr = idx >> 4, cq = idx & 15;
            cp_async16(smem_u32(&S.Bs[buf][kr][cq * 4]),
                       Wt + (size_t)(k0 + kr) * Nc + bn + cq * 4);
        }
        CP_COMMIT();
    };

    issueTile(0, 0);
    CP_WAIT0();
    __syncthreads();

    for (int kt = 0; kt < nk; ++kt) {
        const int cur = kt & 1, nxt = cur ^ 1;
        const bool more = (kt + 1 < nk);
        if (more) issueTile(nxt, (kt + 1) * BK);
#pragma unroll
        for (int ks = 0; ks < 4; ++ks) {
            uint32_t af[TM][4];
#pragma unroll
            for (int tm = 0; tm < TM; ++tm) {
                int r = warp_m * 32 + tm * 16;
                af[tm][0] = S.As[cur][r + g][ks * 8 + cc];
                af[tm][1] = S.As[cur][r + g + 8][ks * 8 + cc];
                af[tm][2] = S.As[cur][r + g][ks * 8 + cc + 4];
                af[tm][3] = S.As[cur][r + g + 8][ks * 8 + cc + 4];
            }
#pragma unroll
            for (int tn = 0; tn < TN; ++tn) {
                int nb = warp_n * 32 + tn * 8;
                uint32_t b0 = S.Bs[cur][ks * 8 + cc][nb + g];
                uint32_t b1 = S.Bs[cur][ks * 8 + cc + 4][nb + g];
#pragma unroll
                for (int tm = 0; tm < TM; ++tm)
                    mma8(acc[tm][tn], af[tm][0], af[tm][1], af[tm][2], af[tm][3], b0, b1);
            }
        }
        if (more) CP_WAIT0();
        __syncthreads();
    }

    const bool wr = ((g & 1) == 0);
#pragma unroll
    for (int tm = 0; tm < TM; ++tm) {
#pragma unroll
        for (int half = 0; half < 2; ++half) {
            int r = bm + warp_m * 32 + tm * 16 + g + half * 8;
#pragma unroll
            for (int tn = 0; tn < TN; ++tn) {
                int col = bn + warp_n * 32 + tn * 8 + 2 * cc;
                float h0 = bng[col] * tanhf(acc[tm][tn][half * 2 + 0] + bias[col]) + bnb[col];
                float h1 = bng[col + 1] * tanhf(acc[tm][tn][half * 2 + 1] + bias[col + 1]) + bnb[col + 1];
                float p0 = 0.5f * (h0 + __shfl_down_sync(0xffffffffu, h0, 4));
                float p1 = 0.5f * (h1 + __shfl_down_sync(0xffffffffu, h1, 4));
                if (wr) {
                    int pr = (r / NIN) * (NIN / 2) + (r % NIN) / 2;
                    *reinterpret_cast<float2*>(Out + (size_t)pr * Nc + col) =
                        make_float2(p0, p1);
                }
            }
        }
    }
}

// ---------------- FC: split-K partials (fp32, deterministic) ----------------
__global__ __launch_bounds__(128) void fc_partial(const float* __restrict__ Flat,
                                                  const float* __restrict__ W) {
    constexpr int KCH = FLATD / 256;   // 128
    const int kb = blockIdx.x * KCH;
    const int tid = threadIdx.x;
    __shared__ float sF[BB][KCH];
    for (int t = tid; t < BB * KCH / 4; t += 128) {
        int b = t / (KCH / 4), kq = t % (KCH / 4);
        *reinterpret_cast<float4*>(&sF[b][kq * 4]) =
            *reinterpret_cast<const float4*>(Flat + (size_t)b * FLATD + kb + kq * 4);
    }
    __syncthreads();

    float4 acc[BB];
#pragma unroll
    for (int b = 0; b < BB; ++b) acc[b] = make_float4(0.f, 0.f, 0.f, 0.f);

    const float* wp = W + (size_t)kb * FC_OUT + tid * 4;
    for (int k = 0; k < KCH; k += 4) {
        float4 w0 = *reinterpret_cast<const float4*>(wp + (size_t)(k + 0) * FC_OUT);
        float4 w1 = *reinterpret_cast<const float4*>(wp + (size_t)(k + 1) * FC_OUT);
        float4 w2 = *reinterpret_cast<const float4*>(wp + (size_t)(k + 2) * FC_OUT);
        float4 w3 = *reinterpret_cast<const float4*>(wp + (size_t)(k + 3) * FC_OUT);
#pragma unroll
        for (int b = 0; b < BB; ++b) {
            float4 f = *reinterpret_cast<float4*>(&sF[b][k]);
            acc[b].x += f.x * w0.x + f.y * w1.x + f.z * w2.x + f.w * w3.x;
            acc[b].y += f.x * w0.y + f.y * w1.y + f.z * w2.y + f.w * w3.y;
            acc[b].z += f.x * w0.z + f.y * w1.z + f.z * w2.z + f.w * w3.z;
            acc[b].w += f.x * w0.w + f.y * w1.w + f.z * w2.w + f.w * w3.w;
        }
    }
#pragma unroll
    for (int b = 0; b < BB; ++b)
        *reinterpret_cast<float4*>(&g_part[blockIdx.x][b * FC_OUT + tid * 4]) = acc[b];
}

__global__ void fc_finalize(const float* __restrict__ fcb, float* __restrict__ out) {
    int idx = blockIdx.x * blockDim.x + threadIdx.x;
    if (idx >= BB * FC_OUT) return;
    int col = idx & (FC_OUT - 1);
    float s = fcb[col];
#pragma unroll 8
    for (int t = 0; t < 256; ++t) s += g_part[t][idx];
    out[idx] = 1.f / (1.f + __expf(-s));
}

// ---------------- launch ----------------
extern "C" void kernel_launch(void* const* d_in, const int* in_sizes, int n_in,
                              void* d_out, int out_size) {
    const float* V    = (const float*)d_in[0];
    const float* C    = (const float*)d_in[1];
    const float* gkw0 = (const float*)d_in[2];
    const float* gkb0 = (const float*)d_in[3];
    const float* acw0 = (const float*)d_in[4];
    const float* acb0 = (const float*)d_in[5];
    const float* gcw0 = (const float*)d_in[6];
    const float* gcb0 = (const float*)d_in[7];
    const float* bng0 = (const float*)d_in[8];
    const float* bnb0 = (const float*)d_in[9];
    const float* gkw1 = (const float*)d_in[10];
    const float* gkb1 = (const float*)d_in[11];
    const float* acw1 = (const float*)d_in[12];
    const float* acb1 = (const float*)d_in[13];
    const float* gcw1 = (const float*)d_in[14];
    const float* gcb1 = (const float*)d_in[15];
    const float* bng1 = (const float*)d_in[16];
    const float* bnb1 = (const float*)d_in[17];
    const float* fcw  = (const float*)d_in[18];
    const float* fcb  = (const float*)d_in[19];
    float* out = (float*)d_out;

    float *X0, *H0p, *C1, *X1, *Flat;
    cudaGetSymbolAddress((void**)&X0, g_X0);
    cudaGetSymbolAddress((void**)&H0p, g_H0p);
    cudaGetSymbolAddress((void**)&C1, g_C1);
    cudaGetSymbolAddress((void**)&X1, g_X1);
    cudaGetSymbolAddress((void**)&Flat, g_Flat);

    const int smsg0 = (int)sizeof(MsgSmem<F0c, 32>);
    const int smsg1 = (int)sizeof(MsgSmem<F1c, 16>);
    const int sgemm = (int)sizeof(GemmSmem);
    cudaFuncSetAttribute(msg_kernel<F0c, N0, 32>,
                         cudaFuncAttributeMaxDynamicSharedMemorySize, smsg0);
    cudaFuncSetAttribute(msg_kernel<F1c, N1, 16>,
                         cudaFuncAttributeMaxDynamicSharedMemorySize, smsg1);
    cudaFuncSetAttribute(gemm_pool<N0>,
                         cudaFuncAttributeMaxDynamicSharedMemorySize, sgemm);
    cudaFuncSetAttribute(gemm_pool<N1>,
                         cudaFuncAttributeMaxDynamicSharedMemorySize, sgemm);

    // layer 0 (msg0 TI=32; coord pooling fused into blockIdx.x==0 blocks)
    msg_kernel<F0c, N0, 32><<<dim3(N0 / 32, BB), 256, smsg0>>>(
        V, C, gkw0, gkb0, acw0, acb0, X0, C1);
    gemm_pool<N0><<<dim3(F1c / 64, BB * N0 / 128), 256, sgemm>>>(
        X0, gcw0, gcb0, bng0, bnb0, H0p, (KK + 1) * F0c, F1c);

    // layer 1 (msg1 TI=16, unchanged)
    msg_kernel<F1c, N1, 16><<<dim3(N1 / 16, BB), 256, smsg1>>>(
        H0p, C1, gkw1, gkb1, acw1, acb1, X1, nullptr);
    gemm_pool<N1><<<dim3(F2c / 64, BB * N1 / 128), 256, sgemm>>>(
        X1, gcw1, gcb1, bng1, bnb1, Flat, (KK + 1) * F1c, F2c);

    // FC head (fp32)
    fc_partial<<<256, 128>>>(Flat, fcw);
    fc_finalize<<<(BB * FC_OUT + 255) / 256, 256>>>(fcb, out);
}

// round 17
// speedup vs baseline: 1.0606x; 1.0348x over previous
#include <cuda_runtime.h>
#include <cstdint>

// ---------------- model constants ----------------
#define BB 16
#define N0 512
#define N1 256
#define N2 128
#define F0c 64
#define F1c 128
#define F2c 256
#define KK 8
#define FC_OUT 512
#define FLATD (N2 * F2c)        // 32768
#define EPSC 1e-9f
#define ZCUT 18.0f

// ---------------- scratch (device globals, no allocs) ----------------
__device__ float g_X0[BB * N0 * (F0c + KK * F0c)];   // [8192, 576]
__device__ float g_H0p[BB * N1 * F1c];
__device__ float g_C1[BB * N1 * 3];
__device__ float g_X1[BB * N1 * (F1c + KK * F1c)];   // [4096, 1152]
__device__ float g_Flat[BB * N2 * F2c];
__device__ float g_part[256][BB * FC_OUT];

// ---------------- helpers ----------------
__device__ __forceinline__ void mma8(float* c,
        uint32_t a0, uint32_t a1, uint32_t a2, uint32_t a3,
        uint32_t b0, uint32_t b1) {
    asm volatile(
        "mma.sync.aligned.m16n8k8.row.col.f32.tf32.tf32.f32 "
        "{%0,%1,%2,%3},{%4,%5,%6,%7},{%8,%9},{%0,%1,%2,%3};"
        : "+f"(c[0]), "+f"(c[1]), "+f"(c[2]), "+f"(c[3])
        : "r"(a0), "r"(a1), "r"(a2), "r"(a3), "r"(b0), "r"(b1));
}
__device__ __forceinline__ uint32_t smem_u32(const void* p) {
    return (uint32_t)__cvta_generic_to_shared(p);
}
__device__ __forceinline__ void cp_async16(uint32_t saddr, const void* gptr) {
    asm volatile("cp.async.ca.shared.global [%0], [%1], 16;"
                 :: "r"(saddr), "l"(gptr));
}
#define CP_COMMIT() asm volatile("cp.async.commit_group;" ::: "memory")
#define CP_WAIT0()  asm volatile("cp.async.wait_group 0;" ::: "memory")
#define CP_WAIT1()  asm volatile("cp.async.wait_group 1;" ::: "memory")

// =================================================================
// Fused message passing (R16, frozen):
//   msg0: F=64,  TI=32, 256 thr  (+ fused coord pooling C->C1)
//   msg1: F=128, TI=16, 256 thr
// =================================================================
template <int F, int TI>
struct MsgSmem {
    float4 Ci[TI];
    float  Rni[TI];
    float  U[TI][KK];
    float  W[TI][KK];
    float  Umin[TI];
    alignas(16) uint32_t A[2][32][TI * 8 + 8];   // AT: [j][m=i*8+k]
    alignas(16) uint32_t Vt[2][32][F + 8];       // [j][f]
    unsigned short wIdx[8][TI * 4];
    float  wD2[8][TI * 4];
    float  wCs[8][TI * 4];
};

template <int F, int N, int TI>
__global__ __launch_bounds__(256, 2) void msg_kernel(
        const float* __restrict__ V, const float* __restrict__ C,
        const float* __restrict__ gkw, const float* __restrict__ gkb,
        const float* __restrict__ acw, const float* __restrict__ acb,
        float* __restrict__ X, float* __restrict__ C1out) {
    constexpr int TJ = 32, XW = F + KK * F;
    constexpr int MROWS = TI * 8;
    constexpr int WARPS_N = F / 32;
    constexpr int WARPS_M = 8 / WARPS_N;
    constexpr int WM = MROWS / WARPS_M;     // 64
    constexpr int WN = 32;
    constexpr int TM = WM / 16;             // 4
    constexpr int TN = WN / 8;              // 4
    constexpr int VLD = TJ * (F / 4) / 256;
    constexpr int T = N / TJ;
    constexpr int NIT = TI / 8;

    extern __shared__ char smem_raw[];
    auto& S = *reinterpret_cast<MsgSmem<F, TI>*>(smem_raw);

    const int b = blockIdx.y;
    const int i0 = blockIdx.x * TI;
    const int tid = threadIdx.x;
    const int wid = tid >> 5, lane = tid & 31;
    const int g = lane >> 2, cc = lane & 3;
    const int warp_m = wid / WARPS_N, warp_n = wid % WARPS_N;

    auto bld_i = [&](int s) {
        return (TI == 16) ? (lane & 15) : lane;
    };
    auto bld_jj = [&](int s) {
        int c = (TI == 16) ? (s * 2 + (lane >> 4)) : s;
        return ((c >> 1) << 4) + wid * 2 + (c & 1);
    };

    // fused coord pooling (layer 0 only)
    if (C1out != nullptr && blockIdx.x == 0) {
        for (int t = tid; t < N1 * 3; t += 256) {
            int c = t % 3, i = t / 3;
            size_t base = ((size_t)b * N0 + 2 * i) * 3 + c;
            C1out[(size_t)b * N1 * 3 + t] = 0.5f * (C[base] + C[base + 3]);
        }
    }

    if (tid < TI) {
        int i = i0 + tid;
        float x = C[((size_t)b * N + i) * 3 + 0];
        float y = C[((size_t)b * N + i) * 3 + 1];
        float z = C[((size_t)b * N + i) * 3 + 2];
        float l2 = x * x + y * y + z * z;
        S.Ci[tid] = make_float4(x, y, z, l2);
        S.Rni[tid] = rsqrtf(l2 + EPSC);
    }
    if (TI == 16) {
        int gate = tid >> 7;
        int r = (tid >> 3) & 15;
        int k = tid & 7;
        const float* wgt = gate ? acw : gkw;
        float s = gate ? acb[k] : gkb[k];
        const float* vrow = V + ((size_t)b * N + i0 + r) * F;
#pragma unroll 8
        for (int f = 0; f < F; ++f) s += vrow[f] * wgt[f * KK + k];
        if (gate) {
            S.W[r][k] = 1.f / (1.f + __expf(-s));
        } else {
            float u = fmaxf(s, 0.f) + log1pf(__expf(-fabsf(s)));
            S.U[r][k] = u;
            float um = u;
            um = fminf(um, __shfl_xor_sync(0xffffffffu, um, 1));
            um = fminf(um, __shfl_xor_sync(0xffffffffu, um, 2));
            um = fminf(um, __shfl_xor_sync(0xffffffffu, um, 4));
            if (k == 0) S.Umin[r] = um;
        }
    } else {
        int r = tid >> 3;
        int k = tid & 7;
        float su = gkb[k], sw = acb[k];
        const float* vrow = V + ((size_t)b * N + i0 + r) * F;
#pragma unroll 8
        for (int f = 0; f < F; ++f) {
            float vv = vrow[f];
            su += vv * gkw[f * KK + k];
            sw += vv * acw[f * KK + k];
        }
        S.W[r][k] = 1.f / (1.f + __expf(-sw));
        float u = fmaxf(su, 0.f) + log1pf(__expf(-fabsf(su)));
        S.U[r][k] = u;
        float um = u;
        um = fminf(um, __shfl_xor_sync(0xffffffffu, um, 1));
        um = fminf(um, __shfl_xor_sync(0xffffffffu, um, 2));
        um = fminf(um, __shfl_xor_sync(0xffffffffu, um, 4));
        if (k == 0) S.Umin[r] = um;
    }
    for (int t = tid; t < TI * (F / 4); t += 256) {
        int i = t / (F / 4), fq = t % (F / 4);
        float4 vv = reinterpret_cast<const float4*>(V + ((size_t)b * N + i0 + i) * F)[fq];
        reinterpret_cast<float4*>(X + ((size_t)b * N + i0 + i) * XW)[fq] = vv;
    }
    __syncthreads();

    auto issueV = [&](int buf, int j0) {
#pragma unroll
        for (int s = 0; s < VLD; ++s) {
            int idx = tid + s * 256;
            int j = idx / (F / 4), fq = idx % (F / 4);
            cp_async16(smem_u32(&S.Vt[buf][j][fq * 4]),
                       V + ((size_t)b * N + j0 + j) * F + fq * 4);
        }
        CP_COMMIT();
    };

    auto build = [&](int buf, const float* cxa, const float* cya, const float* cza) {
        int wcnt = 0;
#pragma unroll
        for (int s = 0; s < NIT; ++s) {
            int i = bld_i(s);
            int jj = bld_jj(s);
            float cx = cxa[s], cy = cya[s], cz = cza[s];
            float l2 = cx * cx + cy * cy + cz * cz;
            float4 ci = S.Ci[i];
            float dot = ci.x * cx + ci.y * cy + ci.z * cz;
            float d2 = fabsf(ci.w + l2 - 2.f * dot) + EPSC;
            bool near = (d2 * S.Umin[i] <= ZCUT);
            if (!near) {
                uint4 z = make_uint4(0u, 0u, 0u, 0u);
                *reinterpret_cast<uint4*>(&S.A[buf][jj][i * 8 + 0]) = z;
                *reinterpret_cast<uint4*>(&S.A[buf][jj][i * 8 + 4]) = z;
            }
            unsigned mask = __ballot_sync(0xffffffffu, near);
            if (near) {
                int slot = wcnt + __popc(mask & ((1u << lane) - 1u));
                S.wIdx[wid][slot] = (unsigned short)((i << 5) | jj);
                S.wD2[wid][slot] = d2;
                S.wCs[wid][slot] = dot * S.Rni[i] * rsqrtf(l2 + EPSC);
            }
            wcnt += __popc(mask);
        }
        __syncwarp();
        const int work = wcnt * 2;
        for (int t = lane; t < work; t += 32) {
            int e = t >> 1, h = t & 1;
            int p = S.wIdx[wid][e];
            int i = p >> 5, jj = p & 31;
            float d2 = S.wD2[wid][e], cs = S.wCs[wid][e];
            float4 uu = *reinterpret_cast<const float4*>(&S.U[i][h * 4]);
            float4 ww = *reinterpret_cast<const float4*>(&S.W[i][h * 4]);
            uint4 o;
            { float z = d2 * uu.x; float ex = (z > ZCUT) ? 0.f : __expf(-z);
              o.x = __float_as_uint(ex * (ww.x * cs + 1.f - ww.x)); }
            { float z = d2 * uu.y; float ex = (z > ZCUT) ? 0.f : __expf(-z);
              o.y = __float_as_uint(ex * (ww.y * cs + 1.f - ww.y)); }
            { float z = d2 * uu.z; float ex = (z > ZCUT) ? 0.f : __expf(-z);
              o.z = __float_as_uint(ex * (ww.z * cs + 1.f - ww.z)); }
            { float z = d2 * uu.w; float ex = (z > ZCUT) ? 0.f : __expf(-z);
              o.w = __float_as_uint(ex * (ww.w * cs + 1.f - ww.w)); }
            *reinterpret_cast<uint4*>(&S.A[buf][jj][i * 8 + h * 4]) = o;
        }
    };

    {
        issueV(0, 0);
        float cxa[NIT], cya[NIT], cza[NIT];
#pragma unroll
        for (int s = 0; s < NIT; ++s) {
            int jj = bld_jj(s);
            const float* cp = C + ((size_t)b * N + jj) * 3;
            cxa[s] = cp[0]; cya[s] = cp[1]; cza[s] = cp[2];
        }
        build(0, cxa, cya, cza);
        CP_WAIT0();
    }
    __syncthreads();

    float acc[TM][TN][4];
#pragma unroll
    for (int tm = 0; tm < TM; ++tm)
#pragma unroll
        for (int tn = 0; tn < TN; ++tn)
#pragma unroll
            for (int q = 0; q < 4; ++q) acc[tm][tn][q] = 0.f;

    for (int t = 0; t < T; ++t) {
        const int cur = t & 1, nxt = cur ^ 1;
        const bool more = (t + 1 < T);
        float cxa[NIT], cya[NIT], cza[NIT];
        if (more) {
            int j0n = (t + 1) * TJ;
            issueV(nxt, j0n);
#pragma unroll
            for (int s = 0; s < NIT; ++s) {
                int jj = bld_jj(s);
                const float* cp = C + ((size_t)b * N + j0n + jj) * 3;
                cxa[s] = cp[0]; cya[s] = cp[1]; cza[s] = cp[2];
            }
        }
#pragma unroll
        for (int ks = 0; ks < 4; ++ks) {
            uint32_t af[TM][4];
#pragma unroll
            for (int tm = 0; tm < TM; ++tm) {
                int r = warp_m * WM + tm * 16;
                af[tm][0] = S.A[cur][ks * 8 + cc][r + g];
                af[tm][1] = S.A[cur][ks * 8 + cc][r + g + 8];
                af[tm][2] = S.A[cur][ks * 8 + cc + 4][r + g];
                af[tm][3] = S.A[cur][ks * 8 + cc + 4][r + g + 8];
            }
#pragma unroll
            for (int tn = 0; tn < TN; ++tn) {
                int nb = warp_n * WN + tn * 8;
                uint32_t b0 = S.Vt[cur][ks * 8 + cc][nb + g];
                uint32_t b1 = S.Vt[cur][ks * 8 + cc + 4][nb + g];
#pragma unroll
                for (int tm = 0; tm < TM; ++tm)
                    mma8(acc[tm][tn], af[tm][0], af[tm][1], af[tm][2], af[tm][3], b0, b1);
            }
        }
        if (more) {
            build(nxt, cxa, cya, cza);
            CP_WAIT0();
        }
        __syncthreads();
    }

#pragma unroll
    for (int tm = 0; tm < TM; ++tm) {
#pragma unroll
        for (int half = 0; half < 2; ++half) {
            int m = warp_m * WM + tm * 16 + g + half * 8;
            int i = m >> 3, k = m & 7;
            float* xr = X + ((size_t)b * N + i0 + i) * XW + F + k * F + warp_n * WN;
#pragma unroll
            for (int tn = 0; tn < TN; ++tn) {
                float2 o;
                o.x = acc[tm][tn][half * 2 + 0];
                o.y = acc[tm][tn][half * 2 + 1];
                *reinterpret_cast<float2*>(xr + tn * 8 + 2 * cc) = o;
            }
        }
    }
}

// =================================================================
// tf32 GEMM + tanh + BN + fused 2:1 row pooling.
// 3-stage cp.async pipeline: copies get ~2 compute phases of slack.
// =================================================================
struct GemmSmem {
    alignas(16) uint32_t As[3][128][36];   // 55296 B
    alignas(16) uint32_t Bs[3][32][72];    // 27648 B
};

template <int NIN>
__global__ __launch_bounds__(256) void gemm_pool(
        const float* __restrict__ A, const float* __restrict__ Wt,
        const float* __restrict__ bias, const float* __restrict__ bng,
        const float* __restrict__ bnb, float* __restrict__ Out,
        int Kd, int Nc) {
    constexpr int BM = 128, BN = 64, BK = 32;
    constexpr int TM = 2, TN = 4;
    extern __shared__ char smem_raw[];
    auto& S = *reinterpret_cast<GemmSmem*>(smem_raw);
    const int bm = blockIdx.y * BM, bn = blockIdx.x * BN;
    const int tid = threadIdx.x, wid = tid >> 5, lane = tid & 31;
    const int g = lane >> 2, cc = lane & 3;
    const int warp_m = wid >> 1, warp_n = wid & 1;

    float acc[TM][TN][4];
#pragma unroll
    for (int tm = 0; tm < TM; ++tm)
#pragma unroll
        for (int tn = 0; tn < TN; ++tn)
#pragma unroll
            for (int q = 0; q < 4; ++q) acc[tm][tn][q] = 0.f;

    const int nk = Kd / BK;

    auto issueTile = [&](int buf, int k0) {
#pragma unroll
        for (int s = 0; s < 4; ++s) {
            int idx = tid + s * 256, r = idx >> 3, cq = idx & 7;
            cp_async16(smem_u32(&S.As[buf][r][cq * 4]),
                       A + (size_t)(bm + r) * Kd + k0 + cq * 4);
        }
#pragma unroll
        for (int s = 0; s < 2; ++s) {
            int idx = tid + s * 256, kr = idx >> 4, cq = idx & 15;
            cp_async16(smem_u32(&S.Bs[buf][kr][cq * 4]),
                       Wt + (size_t)(k0 + kr) * Nc + bn + cq * 4);
        }
        CP_COMMIT();
    };

    // prologue: 2 tiles in flight
    issueTile(0, 0);
    issueTile(1, BK);

    int buf = 0;
    for (int kt = 0; kt < nk; ++kt) {
        CP_WAIT1();          // oldest pending group (tile kt) complete
        __syncthreads();     // data visible to all warps; prior readers done
#pragma unroll
        for (int ks = 0; ks < 4; ++ks) {
            uint32_t af[TM][4];
#pragma unroll
            for (int tm = 0; tm < TM; ++tm) {
                int r = warp_m * 32 + tm * 16;
                af[tm][0] = S.As[buf][r + g][ks * 8 + cc];
                af[tm][1] = S.As[buf][r + g + 8][ks * 8 + cc];
                af[tm][2] = S.As[buf][r + g][ks * 8 + cc + 4];
                af[tm][3] = S.As[buf][r + g + 8][ks * 8 + cc + 4];
            }
#pragma unroll
            for (int tn = 0; tn < TN; ++tn) {
                int nb = warp_n * 32 + tn * 8;
                uint32_t b0 = S.Bs[buf][ks * 8 + cc][nb + g];
                uint32_t b1 = S.Bs[buf][ks * 8 + cc + 4][nb + g];
#pragma unroll
                for (int tm = 0; tm < TM; ++tm)
                    mma8(acc[tm][tn], af[tm][0], af[tm][1], af[tm][2], af[tm][3], b0, b1);
            }
        }
        if (kt + 2 < nk) {
            int nb3 = buf + 2;
            if (nb3 >= 3) nb3 -= 3;
            issueTile(nb3, (kt + 2) * BK);
        } else {
            CP_COMMIT();     // keep group counting aligned for CP_WAIT1
        }
        if (++buf == 3) buf = 0;
    }

    // epilogue: tanh + BN + pool rows (2r,2r+1) via shuffle (row+1 = lane+4)
    const bool wr = ((g & 1) == 0);
#pragma unroll
    for (int tm = 0; tm < TM; ++tm) {
#pragma unroll
        for (int half = 0; half < 2; ++half) {
            int r = bm + warp_m * 32 + tm * 16 + g + half * 8;
#pragma unroll
            for (int tn = 0; tn < TN; ++tn) {
                int col = bn + warp_n * 32 + tn * 8 + 2 * cc;
                float h0 = bng[col] * tanhf(acc[tm][tn][half * 2 + 0] + bias[col]) + bnb[col];
                float h1 = bng[col + 1] * tanhf(acc[tm][tn][half * 2 + 1] + bias[col + 1]) + bnb[col + 1];
                float p0 = 0.5f * (h0 + __shfl_down_sync(0xffffffffu, h0, 4));
                float p1 = 0.5f * (h1 + __shfl_down_sync(0xffffffffu, h1, 4));
                if (wr) {
                    int pr = (r / NIN) * (NIN / 2) + (r % NIN) / 2;
                    *reinterpret_cast<float2*>(Out + (size_t)pr * Nc + col) =
                        make_float2(p0, p1);
                }
            }
        }
    }
}

// ---------------- FC: split-K partials (fp32, deterministic) ----------------
__global__ __launch_bounds__(128) void fc_partial(const float* __restrict__ Flat,
                                                  const float* __restrict__ W) {
    constexpr int KCH = FLATD / 256;   // 128
    const int kb = blockIdx.x * KCH;
    const int tid = threadIdx.x;
    __shared__ float sF[BB][KCH];
    for (int t = tid; t < BB * KCH / 4; t += 128) {
        int b = t / (KCH / 4), kq = t % (KCH / 4);
        *reinterpret_cast<float4*>(&sF[b][kq * 4]) =
            *reinterpret_cast<const float4*>(Flat + (size_t)b * FLATD + kb + kq * 4);
    }
    __syncthreads();

    float4 acc[BB];
#pragma unroll
    for (int b = 0; b < BB; ++b) acc[b] = make_float4(0.f, 0.f, 0.f, 0.f);

    const float* wp = W + (size_t)kb * FC_OUT + tid * 4;
    for (int k = 0; k < KCH; k += 4) {
        float4 w0 = *reinterpret_cast<const float4*>(wp + (size_t)(k + 0) * FC_OUT);
        float4 w1 = *reinterpret_cast<const float4*>(wp + (size_t)(k + 1) * FC_OUT);
        float4 w2 = *reinterpret_cast<const float4*>(wp + (size_t)(k + 2) * FC_OUT);
        float4 w3 = *reinterpret_cast<const float4*>(wp + (size_t)(k + 3) * FC_OUT);
#pragma unroll
        for (int b = 0; b < BB; ++b) {
            float4 f = *reinterpret_cast<float4*>(&sF[b][k]);
            acc[b].x += f.x * w0.x + f.y * w1.x + f.z * w2.x + f.w * w3.x;
            acc[b].y += f.x * w0.y + f.y * w1.y + f.z * w2.y + f.w * w3.y;
            acc[b].z += f.x * w0.z + f.y * w1.z + f.z * w2.z + f.w * w3.z;
            acc[b].w += f.x * w0.w + f.y * w1.w + f.z * w2.w + f.w * w3.w;
        }
    }
#pragma unroll
    for (int b = 0; b < BB; ++b)
        *reinterpret_cast<float4*>(&g_part[blockIdx.x][b * FC_OUT + tid * 4]) = acc[b];
}

__global__ void fc_finalize(const float* __restrict__ fcb, float* __restrict__ out) {
    int idx = blockIdx.x * blockDim.x + threadIdx.x;
    if (idx >= BB * FC_OUT) return;
    int col = idx & (FC_OUT - 1);
    float s = fcb[col];
#pragma unroll 8
    for (int t = 0; t < 256; ++t) s += g_part[t][idx];
    out[idx] = 1.f / (1.f + __expf(-s));
}

// ---------------- launch ----------------
extern "C" void kernel_launch(void* const* d_in, const int* in_sizes, int n_in,
                              void* d_out, int out_size) {
    const float* V    = (const float*)d_in[0];
    const float* C    = (const float*)d_in[1];
    const float* gkw0 = (const float*)d_in[2];
    const float* gkb0 = (const float*)d_in[3];
    const float* acw0 = (const float*)d_in[4];
    const float* acb0 = (const float*)d_in[5];
    const float* gcw0 = (const float*)d_in[6];
    const float* gcb0 = (const float*)d_in[7];
    const float* bng0 = (const float*)d_in[8];
    const float* bnb0 = (const float*)d_in[9];
    const float* gkw1 = (const float*)d_in[10];
    const float* gkb1 = (const float*)d_in[11];
    const float* acw1 = (const float*)d_in[12];
    const float* acb1 = (const float*)d_in[13];
    const float* gcw1 = (const float*)d_in[14];
    const float* gcb1 = (const float*)d_in[15];
    const float* bng1 = (const float*)d_in[16];
    const float* bnb1 = (const float*)d_in[17];
    const float* fcw  = (const float*)d_in[18];
    const float* fcb  = (const float*)d_in[19];
    float* out = (float*)d_out;

    float *X0, *H0p, *C1, *X1, *Flat;
    cudaGetSymbolAddress((void**)&X0, g_X0);
    cudaGetSymbolAddress((void**)&H0p, g_H0p);
    cudaGetSymbolAddress((void**)&C1, g_C1);
    cudaGetSymbolAddress((void**)&X1, g_X1);
    cudaGetSymbolAddress((void**)&Flat, g_Flat);

    const int smsg0 = (int)sizeof(MsgSmem<F0c, 32>);
    const int smsg1 = (int)sizeof(MsgSmem<F1c, 16>);
    const int sgemm = (int)sizeof(GemmSmem);
    cudaFuncSetAttribute(msg_kernel<F0c, N0, 32>,
                         cudaFuncAttributeMaxDynamicSharedMemorySize, smsg0);
    cudaFuncSetAttribute(msg_kernel<F1c, N1, 16>,
                         cudaFuncAttributeMaxDynamicSharedMemorySize, smsg1);
    cudaFuncSetAttribute(gemm_pool<N0>,
                         cudaFuncAttributeMaxDynamicSharedMemorySize, sgemm);
    cudaFuncSetAttribute(gemm_pool<N1>,
                         cudaFuncAttributeMaxDynamicSharedMemorySize, sgemm);

    // layer 0 (msg0 TI=32; coord pooling fused)
    msg_kernel<F0c, N0, 32><<<dim3(N0 / 32, BB), 256, smsg0>>>(
        V, C, gkw0, gkb0, acw0, acb0, X0, C1);
    gemm_pool<N0><<<dim3(F1c / 64, BB * N0 / 128), 256, sgemm>>>(
        X0, gcw0, gcb0, bng0, bnb0, H0p, (KK + 1) * F0c, F1c);

    // layer 1 (msg1 TI=16)
    msg_kernel<F1c, N1, 16><<<dim3(N1 / 16, BB), 256, smsg1>>>(
        H0p, C1, gkw1, gkb1, acw1, acb1, X1, nullptr);
    gemm_pool<N1><<<dim3(F2c / 64, BB * N1 / 128), 256, sgemm>>>(
        X1, gcw1, gcb1, bng1, bnb1, Flat, (KK + 1) * F1c, F2c);

    // FC head (fp32)
    fc_partial<<<256, 128>>>(Flat, fcw);
    fc_finalize<<<(BB * FC_OUT + 255) / 256, 256>>>(fcb, out);
}